// round 9
// baseline (speedup 1.0000x reference)
#include <cuda_runtime.h>
#include <math.h>
#include <stdint.h>

#define NN 500000
#define FF 128
#define HH 64
#define BB 1024
#define TILE 128
#define XS_STRIDE 132
#define WB_STRIDE 68   // u32 stride for packed bf16 W tiles (conflict-free frag loads)

// ---------------- scratch (no allocations allowed) ----------------
__device__ int2  g_spair[2][NN];      // (node idx, segment) in segment-sorted order
__device__ int   g_count[2][BB];
__device__ int   g_cursor[2][BB];
__device__ float g_acc[2][BB * FF];   // unnormalized e*x sums
__device__ float g_s[2][BB];          // unnormalized e sums
// pre-split W1^T packed bf16x2: [n 0..63][kp 0..63], kp = k/2 (k even in low half)
__device__ uint32_t g_wb_hi[HH * 64];
__device__ uint32_t g_wb_lo[HH * 64];

// ---------------- helpers ----------------
__device__ __forceinline__ uint32_t bf16x2_pack(float up, float lo) {
    uint32_t d;
    asm("cvt.rn.bf16x2.f32 %0, %1, %2;" : "=r"(d) : "f"(up), "f"(lo));
    return d;
}
__device__ __forceinline__ float bf16_lo_as_f32(uint32_t u) { return __uint_as_float(u << 16); }
__device__ __forceinline__ float bf16_hi_as_f32(uint32_t u) { return __uint_as_float(u & 0xFFFF0000u); }

__device__ __forceinline__ float tanh_fast(float v) {
    float e = __expf(2.0f * v);
    return 1.0f - __fdividef(2.0f, e + 1.0f);
}
__device__ __forceinline__ void mma_bf16(float* c, const uint32_t* a, const uint32_t* b) {
    asm volatile(
        "mma.sync.aligned.m16n8k16.row.col.f32.bf16.bf16.f32 "
        "{%0,%1,%2,%3}, {%4,%5,%6,%7}, {%8,%9}, {%0,%1,%2,%3};"
        : "+f"(c[0]), "+f"(c[1]), "+f"(c[2]), "+f"(c[3])
        : "r"(a[0]), "r"(a[1]), "r"(a[2]), "r"(a[3]), "r"(b[0]), "r"(b[1]));
}
__device__ __forceinline__ void split2(float2 q, uint32_t& hi, uint32_t& lo) {
    hi = bf16x2_pack(q.y, q.x);
    float hx = bf16_lo_as_f32(hi);
    float hy = bf16_hi_as_f32(hi);
    lo = bf16x2_pack(q.y - hy, q.x - hx);
}

// ---------------- K0: init (zero accumulators + counters) ----------------
__global__ void init_kernel() {
    int i = blockIdx.x * blockDim.x + threadIdx.x;
    if (i < 2 * BB * FF) (&g_acc[0][0])[i] = 0.0f;
    if (i < 2 * BB) {
        (&g_s[0][0])[i] = 0.0f;
        (&g_count[0][0])[i] = 0;
    }
}

// ---------------- K0b: pre-split + pre-pack W1 ----------------
__global__ void prep_w_kernel(const float* __restrict__ W1) {
    int i = blockIdx.x * blockDim.x + threadIdx.x;
    if (i >= HH * 64) return;
    int n  = i >> 6;
    int kp = i & 63;
    float w0 = W1[(2 * kp)     * HH + n];
    float w1 = W1[(2 * kp + 1) * HH + n];
    uint32_t hi = bf16x2_pack(w1, w0);
    float h0 = bf16_lo_as_f32(hi);
    float h1 = bf16_hi_as_f32(hi);
    uint32_t lo = bf16x2_pack(w1 - h1, w0 - h0);
    g_wb_hi[i] = hi;
    g_wb_lo[i] = lo;
}

// ---------------- K1: histogram of batch ids ----------------
__global__ __launch_bounds__(512) void hist_kernel(
    const int* __restrict__ bA, const int* __restrict__ bB)
{
    int t = blockIdx.y;
    int i0 = (blockIdx.x * 512 + threadIdx.x) * 4;
    if (i0 >= NN) return;   // NN % 4 == 0
    const int* batch = t ? bB : bA;
    int4 bv = *(const int4*)&batch[i0];
    atomicAdd(&g_count[t][bv.x], 1);
    atomicAdd(&g_count[t][bv.y], 1);
    atomicAdd(&g_count[t][bv.z], 1);
    atomicAdd(&g_count[t][bv.w], 1);
}

// ---------------- K2: exclusive prefix scan over segments ----------------
__global__ void scan_kernel() {
    __shared__ int ss[BB];
    int tid = threadIdx.x;
    for (int t = 0; t < 2; ++t) {
        int v = g_count[t][tid];
        ss[tid] = v;
        __syncthreads();
        for (int d = 1; d < BB; d <<= 1) {
            int add = (tid >= d) ? ss[tid - d] : 0;
            __syncthreads();
            ss[tid] += add;
            __syncthreads();
        }
        g_cursor[t][tid] = ss[tid] - v;
        __syncthreads();
    }
}

// ---------------- K3: scatter (node, seg) into segment-sorted order ----------------
__global__ __launch_bounds__(512) void scatter_kernel(
    const int* __restrict__ bA, const int* __restrict__ bB)
{
    int t = blockIdx.y;
    int i0 = (blockIdx.x * 512 + threadIdx.x) * 4;
    if (i0 >= NN) return;   // NN % 4 == 0
    const int* batch = t ? bB : bA;
    int4 bv = *(const int4*)&batch[i0];
    int p0 = atomicAdd(&g_cursor[t][bv.x], 1);
    int p1 = atomicAdd(&g_cursor[t][bv.y], 1);
    int p2 = atomicAdd(&g_cursor[t][bv.z], 1);
    int p3 = atomicAdd(&g_cursor[t][bv.w], 1);
    g_spair[t][p0] = make_int2(i0 + 0, bv.x);
    g_spair[t][p1] = make_int2(i0 + 1, bv.y);
    g_spair[t][p2] = make_int2(i0 + 2, bv.z);
    g_spair[t][p3] = make_int2(i0 + 3, bv.w);
}

// ---------------- K4: fused score + pool kernel ----------------
// smem: xs[128][132] gathered x rows (f32), swh/swl packed bf16x2 W,
//       b1s[64], w2s[64], es[128], sseg[128], ssid[128]
#define SMEM_WORDS (TILE * XS_STRIDE + 2 * (HH * WB_STRIDE) + 64 + 64 + TILE + TILE + TILE)

__global__ __launch_bounds__(128) void score_pool_kernel(
    const float* __restrict__ x1, const float* __restrict__ x2,
    const float* __restrict__ b1v, const float* __restrict__ W2)
{
    extern __shared__ float sm[];
    float*    xs   = sm;
    uint32_t* swh  = (uint32_t*)(xs + TILE * XS_STRIDE);
    uint32_t* swl  = swh + HH * WB_STRIDE;
    float*    b1s  = (float*)(swl + HH * WB_STRIDE);
    float*    w2s  = b1s + 64;
    float*    es   = w2s + 64;
    int*      sseg = (int*)(es + TILE);
    int*      ssid = sseg + TILE;

    const int tid  = threadIdx.x;
    const int wid  = tid >> 5;
    const int lane = tid & 31;
    const int g    = lane >> 2;
    const int tq   = lane & 3;
    const int t    = blockIdx.y;
    const float* x = t ? x2 : x1;
    const int n0   = blockIdx.x * TILE;

    // load sorted (node, seg) for this tile; padding clamps to last element, e forced to 0
    {
        int pos = n0 + tid;
        int2 pr = g_spair[t][pos < NN ? pos : (NN - 1)];
        ssid[tid] = pr.x;
        sseg[tid] = pr.y;
    }

    // stage packed W (hi+lo)
    #pragma unroll
    for (int m = 0; m < 32; ++m) {
        int j = tid + 128 * m;
        int n  = j >> 6;
        int kp = j & 63;
        swh[n * WB_STRIDE + kp] = g_wb_hi[j];
        swl[n * WB_STRIDE + kp] = g_wb_lo[j];
    }
    if (tid < HH) { b1s[tid] = b1v[tid]; w2s[tid] = W2[tid]; }
    __syncthreads();

    // stage x tile: gather sorted rows (512B coalesced float4 per row)
    #pragma unroll
    for (int m = 0; m < 32; ++m) {
        int idx = m * 128 + tid;
        int r = idx >> 5;
        int q = idx & 31;
        int pos = n0 + r;
        float4 v = make_float4(0.f, 0.f, 0.f, 0.f);
        if (pos < NN) v = ((const float4*)x)[(long)ssid[r] * 32 + q];
        *(float4*)&xs[r * XS_STRIDE + q * 4] = v;
    }
    __syncthreads();

    const int base = wid * 32;
    float acc[2][8][4];
    #pragma unroll
    for (int m = 0; m < 2; ++m)
        #pragma unroll
        for (int n = 0; n < 8; ++n)
            #pragma unroll
            for (int c = 0; c < 4; ++c) acc[m][n][c] = 0.0f;

    #pragma unroll
    for (int kt = 0; kt < 8; ++kt) {
        const int k0  = kt * 16;
        const int kp0 = kt * 8;

        uint32_t bh[8][2], bl[8][2];
        #pragma unroll
        for (int n = 0; n < 8; ++n) {
            int row = (n * 8 + g) * WB_STRIDE + kp0 + tq;
            bh[n][0] = swh[row];
            bh[n][1] = swh[row + 4];
            bl[n][0] = swl[row];
            bl[n][1] = swl[row + 4];
        }

        #pragma unroll
        for (int m = 0; m < 2; ++m) {
            const int r = base + m * 16 + g;
            float2 q0 = *(const float2*)&xs[r       * XS_STRIDE + k0 + 2 * tq];
            float2 q1 = *(const float2*)&xs[(r + 8) * XS_STRIDE + k0 + 2 * tq];
            float2 q2 = *(const float2*)&xs[r       * XS_STRIDE + k0 + 2 * tq + 8];
            float2 q3 = *(const float2*)&xs[(r + 8) * XS_STRIDE + k0 + 2 * tq + 8];

            uint32_t ahi[4], alo[4];
            split2(q0, ahi[0], alo[0]);
            split2(q1, ahi[1], alo[1]);
            split2(q2, ahi[2], alo[2]);
            split2(q3, ahi[3], alo[3]);

            #pragma unroll
            for (int n = 0; n < 8; ++n) {
                mma_bf16(acc[m][n], ahi, bh[n]);
                mma_bf16(acc[m][n], ahi, bl[n]);
                mma_bf16(acc[m][n], alo, bh[n]);
            }
        }
    }

    // epilogue: tanh + W2 dot -> e, stored to smem (no global writes here)
    #pragma unroll
    for (int m = 0; m < 2; ++m) {
        #pragma unroll
        for (int half = 0; half < 2; ++half) {
            float s = 0.0f;
            #pragma unroll
            for (int n = 0; n < 8; ++n) {
                #pragma unroll
                for (int c = 0; c < 2; ++c) {
                    int col = n * 8 + 2 * tq + c;
                    float h = acc[m][half * 8 + 0][0]; // placeholder avoided below
                }
            }
            (void)0;
        }
    }
    // (real epilogue, kept explicit and simple)
    #pragma unroll
    for (int m = 0; m < 2; ++m) {
        #pragma unroll
        for (int half = 0; half < 2; ++half) {
            float s = 0.0f;
            #pragma unroll
            for (int n = 0; n < 8; ++n) {
                #pragma unroll
                for (int c = 0; c < 2; ++c) {
                    int col = n * 8 + 2 * tq + c;
                    float h = acc[m][n][half * 2 + c] + b1s[col];
                    s = fmaf(tanh_fast(h), w2s[col], s);
                }
            }
            s += __shfl_xor_sync(0xffffffffu, s, 1);
            s += __shfl_xor_sync(0xffffffffu, s, 2);
            if (tq == 0) {
                int r = base + m * 16 + half * 8 + g;
                es[r] = (n0 + r < NN) ? __expf(s) : 0.0f;
            }
        }
    }
    __syncthreads();

    // pooling sweep: thread = feature f; segments are contiguous in the tile
    {
        const int f = tid;
        float pacc = 0.0f, eac = 0.0f;
        int cur = sseg[0];
        #pragma unroll 4
        for (int n = 0; n < TILE; ++n) {
            int b = sseg[n];
            if (b != cur) {
                atomicAdd(&g_acc[t][cur * FF + f], pacc);
                if (f == 0) atomicAdd(&g_s[t][cur], eac);
                pacc = 0.0f; eac = 0.0f; cur = b;
            }
            float e = es[n];
            pacc = fmaf(e, xs[n * XS_STRIDE + f], pacc);
            eac += e;
        }
        atomicAdd(&g_acc[t][cur * FF + f], pacc);
        if (f == 0) atomicAdd(&g_s[t][cur], eac);
    }
}

// ---------------- K5: finalize ----------------
__global__ void finalize_kernel(float* __restrict__ out) {
    int i = blockIdx.x * blockDim.x + threadIdx.x;
    if (i >= BB * FF) return;
    int b = i >> 7;
    float s0 = g_s[0][b], s1 = g_s[1][b];
    float r0 = (s0 > 0.0f) ? g_acc[0][i] / s0 : 0.0f;
    float r1 = (s1 > 0.0f) ? g_acc[1][i] / s1 : 0.0f;
    out[i] = 0.5f * (r0 + r1);
}

// ---------------- launch ----------------
extern "C" void kernel_launch(void* const* d_in, const int* in_sizes, int n_in,
                              void* d_out, int out_size) {
    const float *x1 = 0, *x2 = 0, *W1 = 0, *b1v = 0, *W2 = 0;
    const int *bt1 = 0, *bt2 = 0;
    for (int k = 0; k < n_in; ++k) {
        long s = in_sizes[k];
        if (s == (long)NN * FF) { if (!x1) x1 = (const float*)d_in[k]; else if (!x2) x2 = (const float*)d_in[k]; }
        else if (s == NN)       { if (!bt1) bt1 = (const int*)d_in[k]; else if (!bt2) bt2 = (const int*)d_in[k]; }
        else if (s == FF * HH)  { W1 = (const float*)d_in[k]; }
        else if (s == HH)       { if (!b1v) b1v = (const float*)d_in[k]; else if (!W2) W2 = (const float*)d_in[k]; }
    }
    float* out = (float*)d_out;

    init_kernel<<<(2 * BB * FF + 1023) / 1024, 1024>>>();
    prep_w_kernel<<<(HH * 64 + 255) / 256, 256>>>(W1);

    dim3 gh((NN / 4 + 511) / 512, 2);
    hist_kernel<<<gh, 512>>>(bt1, bt2);

    scan_kernel<<<1, BB>>>();

    scatter_kernel<<<gh, 512>>>(bt1, bt2);

    const int smem_bytes = SMEM_WORDS * (int)sizeof(float);
    cudaFuncSetAttribute(score_pool_kernel, cudaFuncAttributeMaxDynamicSharedMemorySize, smem_bytes);
    dim3 g1((NN + TILE - 1) / TILE, 2);
    score_pool_kernel<<<g1, 128, smem_bytes>>>(x1, x2, b1v, W2);

    finalize_kernel<<<(BB * FF + 255) / 256, 256>>>(out);
}

// round 10
// speedup vs baseline: 1.4143x; 1.4143x over previous
#include <cuda_runtime.h>
#include <math.h>
#include <stdint.h>

#define NN 500000
#define FF 128
#define HH 64
#define BB 1024
#define TILE 128
#define XS_STRIDE 132
#define WB_STRIDE 68   // u32 stride for packed bf16 W tiles (conflict-free frag loads)

// ---------------- scratch (no allocations allowed) ----------------
__device__ int2  g_spair[2][NN];      // (node idx, segment) in segment-sorted order
__device__ int   g_count[2][BB];
__device__ int   g_cursor[2][BB];
__device__ float g_acc[2][BB * FF];   // unnormalized e*x sums
__device__ float g_s[2][BB];          // unnormalized e sums
// pre-split W1^T packed bf16x2: [n 0..63][kp 0..63], kp = k/2 (k even in low half)
__device__ uint32_t g_wb_hi[HH * 64];
__device__ uint32_t g_wb_lo[HH * 64];

// ---------------- helpers ----------------
__device__ __forceinline__ uint32_t bf16x2_pack(float up, float lo) {
    uint32_t d;
    asm("cvt.rn.bf16x2.f32 %0, %1, %2;" : "=r"(d) : "f"(up), "f"(lo));
    return d;
}
__device__ __forceinline__ float bf16_lo_as_f32(uint32_t u) { return __uint_as_float(u << 16); }
__device__ __forceinline__ float bf16_hi_as_f32(uint32_t u) { return __uint_as_float(u & 0xFFFF0000u); }

__device__ __forceinline__ float tanh_fast(float v) {
    float e = __expf(2.0f * v);
    return 1.0f - __fdividef(2.0f, e + 1.0f);
}
__device__ __forceinline__ void mma_bf16(float* c, const uint32_t* a, const uint32_t* b) {
    asm volatile(
        "mma.sync.aligned.m16n8k16.row.col.f32.bf16.bf16.f32 "
        "{%0,%1,%2,%3}, {%4,%5,%6,%7}, {%8,%9}, {%0,%1,%2,%3};"
        : "+f"(c[0]), "+f"(c[1]), "+f"(c[2]), "+f"(c[3])
        : "r"(a[0]), "r"(a[1]), "r"(a[2]), "r"(a[3]), "r"(b[0]), "r"(b[1]));
}
__device__ __forceinline__ void split2(float2 q, uint32_t& hi, uint32_t& lo) {
    hi = bf16x2_pack(q.y, q.x);
    float hx = bf16_lo_as_f32(hi);
    float hy = bf16_hi_as_f32(hi);
    lo = bf16x2_pack(q.y - hy, q.x - hx);
}

// ---------------- K0: init (zero accumulators + counters) ----------------
__global__ void init_kernel() {
    int i = blockIdx.x * blockDim.x + threadIdx.x;
    if (i < 2 * BB * FF) (&g_acc[0][0])[i] = 0.0f;
    if (i < 2 * BB) {
        (&g_s[0][0])[i] = 0.0f;
        (&g_count[0][0])[i] = 0;
    }
}

// ---------------- K0b: pre-split + pre-pack W1 ----------------
__global__ void prep_w_kernel(const float* __restrict__ W1) {
    int i = blockIdx.x * blockDim.x + threadIdx.x;
    if (i >= HH * 64) return;
    int n  = i >> 6;
    int kp = i & 63;
    float w0 = W1[(2 * kp)     * HH + n];
    float w1 = W1[(2 * kp + 1) * HH + n];
    uint32_t hi = bf16x2_pack(w1, w0);
    float h0 = bf16_lo_as_f32(hi);
    float h1 = bf16_hi_as_f32(hi);
    uint32_t lo = bf16x2_pack(w1 - h1, w0 - h0);
    g_wb_hi[i] = hi;
    g_wb_lo[i] = lo;
}

// ---------------- K1: histogram of batch ids ----------------
__global__ __launch_bounds__(512) void hist_kernel(
    const int* __restrict__ bA, const int* __restrict__ bB)
{
    int t = blockIdx.y;
    int i0 = (blockIdx.x * 512 + threadIdx.x) * 4;
    if (i0 >= NN) return;   // NN % 4 == 0
    const int* batch = t ? bB : bA;
    int4 bv = *(const int4*)&batch[i0];
    atomicAdd(&g_count[t][bv.x], 1);
    atomicAdd(&g_count[t][bv.y], 1);
    atomicAdd(&g_count[t][bv.z], 1);
    atomicAdd(&g_count[t][bv.w], 1);
}

// ---------------- K2: exclusive prefix scan over segments ----------------
__global__ void scan_kernel() {
    __shared__ int ss[BB];
    int tid = threadIdx.x;
    for (int t = 0; t < 2; ++t) {
        int v = g_count[t][tid];
        ss[tid] = v;
        __syncthreads();
        for (int d = 1; d < BB; d <<= 1) {
            int add = (tid >= d) ? ss[tid - d] : 0;
            __syncthreads();
            ss[tid] += add;
            __syncthreads();
        }
        g_cursor[t][tid] = ss[tid] - v;
        __syncthreads();
    }
}

// ---------------- K3: scatter (node, seg) into segment-sorted order ----------------
__global__ __launch_bounds__(512) void scatter_kernel(
    const int* __restrict__ bA, const int* __restrict__ bB)
{
    int t = blockIdx.y;
    int i0 = (blockIdx.x * 512 + threadIdx.x) * 4;
    if (i0 >= NN) return;   // NN % 4 == 0
    const int* batch = t ? bB : bA;
    int4 bv = *(const int4*)&batch[i0];
    int p0 = atomicAdd(&g_cursor[t][bv.x], 1);
    int p1 = atomicAdd(&g_cursor[t][bv.y], 1);
    int p2 = atomicAdd(&g_cursor[t][bv.z], 1);
    int p3 = atomicAdd(&g_cursor[t][bv.w], 1);
    g_spair[t][p0] = make_int2(i0 + 0, bv.x);
    g_spair[t][p1] = make_int2(i0 + 1, bv.y);
    g_spair[t][p2] = make_int2(i0 + 2, bv.z);
    g_spair[t][p3] = make_int2(i0 + 3, bv.w);
}

// ---------------- K4: fused score + pool kernel (256 threads / 8 GEMM warps) ----------------
// smem: xs[128][132] gathered x rows (f32), swh/swl packed bf16x2 W,
//       b1s[64], w2s[64], es[128], sseg[128], ssid[128]
#define SMEM_WORDS (TILE * XS_STRIDE + 2 * (HH * WB_STRIDE) + 64 + 64 + TILE + TILE + TILE)

__global__ __launch_bounds__(256) void score_pool_kernel(
    const float* __restrict__ x1, const float* __restrict__ x2,
    const float* __restrict__ b1v, const float* __restrict__ W2)
{
    extern __shared__ float sm[];
    float*    xs   = sm;
    uint32_t* swh  = (uint32_t*)(xs + TILE * XS_STRIDE);
    uint32_t* swl  = swh + HH * WB_STRIDE;
    float*    b1s  = (float*)(swl + HH * WB_STRIDE);
    float*    w2s  = b1s + 64;
    float*    es   = w2s + 64;
    int*      sseg = (int*)(es + TILE);
    int*      ssid = sseg + TILE;

    const int tid  = threadIdx.x;
    const int wid  = tid >> 5;      // 0..7, each warp owns 16 rows
    const int lane = tid & 31;
    const int g    = lane >> 2;
    const int tq   = lane & 3;
    const int t    = blockIdx.y;
    const float* x = t ? x2 : x1;
    const int n0   = blockIdx.x * TILE;

    // load sorted (node, seg) for this tile; padding clamps to last element, e forced to 0
    if (tid < TILE) {
        int pos = n0 + tid;
        int2 pr = g_spair[t][pos < NN ? pos : (NN - 1)];
        ssid[tid] = pr.x;
        sseg[tid] = pr.y;
    }

    // stage packed W (hi+lo): 4096 u32 each
    #pragma unroll
    for (int m = 0; m < 16; ++m) {
        int j = tid + 256 * m;
        int n  = j >> 6;
        int kp = j & 63;
        swh[n * WB_STRIDE + kp] = g_wb_hi[j];
        swl[n * WB_STRIDE + kp] = g_wb_lo[j];
    }
    if (tid < HH) { b1s[tid] = b1v[tid]; w2s[tid] = W2[tid]; }
    __syncthreads();

    // stage x tile: gather sorted rows (512B coalesced float4 per row)
    #pragma unroll
    for (int m = 0; m < 16; ++m) {
        int idx = m * 256 + tid;
        int r = idx >> 5;
        int q = idx & 31;
        int pos = n0 + r;
        float4 v = make_float4(0.f, 0.f, 0.f, 0.f);
        if (pos < NN) v = ((const float4*)x)[(long)ssid[r] * 32 + q];
        *(float4*)&xs[r * XS_STRIDE + q * 4] = v;
    }
    __syncthreads();

    // GEMM: each warp computes rows [wid*16, wid*16+16) x 64 hidden
    const int base = wid * 16;
    float acc[8][4];
    #pragma unroll
    for (int n = 0; n < 8; ++n)
        #pragma unroll
        for (int c = 0; c < 4; ++c) acc[n][c] = 0.0f;

    #pragma unroll
    for (int kt = 0; kt < 8; ++kt) {
        const int k0  = kt * 16;
        const int kp0 = kt * 8;

        uint32_t bh[8][2], bl[8][2];
        #pragma unroll
        for (int n = 0; n < 8; ++n) {
            int row = (n * 8 + g) * WB_STRIDE + kp0 + tq;
            bh[n][0] = swh[row];
            bh[n][1] = swh[row + 4];
            bl[n][0] = swl[row];
            bl[n][1] = swl[row + 4];
        }

        const int r = base + g;
        float2 q0 = *(const float2*)&xs[r       * XS_STRIDE + k0 + 2 * tq];
        float2 q1 = *(const float2*)&xs[(r + 8) * XS_STRIDE + k0 + 2 * tq];
        float2 q2 = *(const float2*)&xs[r       * XS_STRIDE + k0 + 2 * tq + 8];
        float2 q3 = *(const float2*)&xs[(r + 8) * XS_STRIDE + k0 + 2 * tq + 8];

        uint32_t ahi[4], alo[4];
        split2(q0, ahi[0], alo[0]);
        split2(q1, ahi[1], alo[1]);
        split2(q2, ahi[2], alo[2]);
        split2(q3, ahi[3], alo[3]);

        #pragma unroll
        for (int n = 0; n < 8; ++n) {
            mma_bf16(acc[n], ahi, bh[n]);
            mma_bf16(acc[n], ahi, bl[n]);
            mma_bf16(acc[n], alo, bh[n]);
        }
    }

    // epilogue: tanh + W2 dot -> e, stored to smem
    #pragma unroll
    for (int half = 0; half < 2; ++half) {
        float s = 0.0f;
        #pragma unroll
        for (int n = 0; n < 8; ++n) {
            #pragma unroll
            for (int c = 0; c < 2; ++c) {
                int col = n * 8 + 2 * tq + c;
                float h = acc[n][half * 2 + c] + b1s[col];
                s = fmaf(tanh_fast(h), w2s[col], s);
            }
        }
        s += __shfl_xor_sync(0xffffffffu, s, 1);
        s += __shfl_xor_sync(0xffffffffu, s, 2);
        if (tq == 0) {
            int r = base + half * 8 + g;
            es[r] = (n0 + r < NN) ? __expf(s) : 0.0f;
        }
    }
    __syncthreads();

    // pooling sweep: thread = (feature f, tile-half h); 64 nodes per thread
    {
        const int f = tid & 127;
        const int h = tid >> 7;
        const int nb = h * 64;
        float pacc = 0.0f, eac = 0.0f;
        int cur = sseg[nb];
        #pragma unroll 4
        for (int n = nb; n < nb + 64; ++n) {
            int b = sseg[n];
            if (b != cur) {
                atomicAdd(&g_acc[t][cur * FF + f], pacc);
                if (f == 0) atomicAdd(&g_s[t][cur], eac);
                pacc = 0.0f; eac = 0.0f; cur = b;
            }
            float e = es[n];
            pacc = fmaf(e, xs[n * XS_STRIDE + f], pacc);
            eac += e;
        }
        atomicAdd(&g_acc[t][cur * FF + f], pacc);
        if (f == 0) atomicAdd(&g_s[t][cur], eac);
    }
}

// ---------------- K5: finalize ----------------
__global__ void finalize_kernel(float* __restrict__ out) {
    int i = blockIdx.x * blockDim.x + threadIdx.x;
    if (i >= BB * FF) return;
    int b = i >> 7;
    float s0 = g_s[0][b], s1 = g_s[1][b];
    float r0 = (s0 > 0.0f) ? g_acc[0][i] / s0 : 0.0f;
    float r1 = (s1 > 0.0f) ? g_acc[1][i] / s1 : 0.0f;
    out[i] = 0.5f * (r0 + r1);
}

// ---------------- launch ----------------
extern "C" void kernel_launch(void* const* d_in, const int* in_sizes, int n_in,
                              void* d_out, int out_size) {
    const float *x1 = 0, *x2 = 0, *W1 = 0, *b1v = 0, *W2 = 0;
    const int *bt1 = 0, *bt2 = 0;
    for (int k = 0; k < n_in; ++k) {
        long s = in_sizes[k];
        if (s == (long)NN * FF) { if (!x1) x1 = (const float*)d_in[k]; else if (!x2) x2 = (const float*)d_in[k]; }
        else if (s == NN)       { if (!bt1) bt1 = (const int*)d_in[k]; else if (!bt2) bt2 = (const int*)d_in[k]; }
        else if (s == FF * HH)  { W1 = (const float*)d_in[k]; }
        else if (s == HH)       { if (!b1v) b1v = (const float*)d_in[k]; else if (!W2) W2 = (const float*)d_in[k]; }
    }
    float* out = (float*)d_out;

    init_kernel<<<(2 * BB * FF + 1023) / 1024, 1024>>>();
    prep_w_kernel<<<(HH * 64 + 255) / 256, 256>>>(W1);

    dim3 gh((NN / 4 + 511) / 512, 2);
    hist_kernel<<<gh, 512>>>(bt1, bt2);

    scan_kernel<<<1, BB>>>();

    scatter_kernel<<<gh, 512>>>(bt1, bt2);

    const int smem_bytes = SMEM_WORDS * (int)sizeof(float);
    cudaFuncSetAttribute(score_pool_kernel, cudaFuncAttributeMaxDynamicSharedMemorySize, smem_bytes);
    dim3 g1((NN + TILE - 1) / TILE, 2);
    score_pool_kernel<<<g1, 256, smem_bytes>>>(x1, x2, b1v, W2);

    finalize_kernel<<<(BB * FF + 255) / 256, 256>>>(out);
}

// round 11
// speedup vs baseline: 2.1147x; 1.4952x over previous
#include <cuda_runtime.h>
#include <math.h>
#include <stdint.h>

#define NN 500000
#define FF 128
#define HH 64
#define BB 1024
#define TILE 128
#define XS_STRIDE 132
#define WB_STRIDE 68   // u32 stride for packed bf16 W tiles (conflict-free frag loads)

// ---------------- scratch (no allocations allowed) ----------------
__device__ float  g_e[2][NN];
__device__ float2 g_pair[2][NN];      // (idx-as-float-bits, e) in segment-sorted order
__device__ int    g_count[2][BB];
__device__ int    g_offset[2][BB + 1];
__device__ int    g_cursor[2][BB];
// pre-split W1^T packed bf16x2: [n 0..63][kp 0..63], kp = k/2 (k even in low half)
__device__ uint32_t g_wb_hi[HH * 64];
__device__ uint32_t g_wb_lo[HH * 64];

// ---------------- helpers ----------------
__device__ __forceinline__ uint32_t bf16x2_pack(float up, float lo) {
    uint32_t d;
    asm("cvt.rn.bf16x2.f32 %0, %1, %2;" : "=r"(d) : "f"(up), "f"(lo));
    return d;
}
__device__ __forceinline__ float bf16_lo_as_f32(uint32_t u) { return __uint_as_float(u << 16); }
__device__ __forceinline__ float bf16_hi_as_f32(uint32_t u) { return __uint_as_float(u & 0xFFFF0000u); }

__device__ __forceinline__ float tanh_fast(float v) {
    float e = __expf(2.0f * v);
    return 1.0f - __fdividef(2.0f, e + 1.0f);
}
__device__ __forceinline__ void mma_bf16(float* c, const uint32_t* a, const uint32_t* b) {
    asm volatile(
        "mma.sync.aligned.m16n8k16.row.col.f32.bf16.bf16.f32 "
        "{%0,%1,%2,%3}, {%4,%5,%6,%7}, {%8,%9}, {%0,%1,%2,%3};"
        : "+f"(c[0]), "+f"(c[1]), "+f"(c[2]), "+f"(c[3])
        : "r"(a[0]), "r"(a[1]), "r"(a[2]), "r"(a[3]), "r"(b[0]), "r"(b[1]));
}
__device__ __forceinline__ void split2(float2 q, uint32_t& hi, uint32_t& lo) {
    hi = bf16x2_pack(q.y, q.x);
    float hx = bf16_lo_as_f32(hi);
    float hy = bf16_hi_as_f32(hi);
    lo = bf16x2_pack(q.y - hy, q.x - hx);
}

// ---------------- K0: init ----------------
__global__ void init_kernel(float* __restrict__ out) {
    int i = blockIdx.x * blockDim.x + threadIdx.x;
    if (i < BB * FF) out[i] = 0.0f;
    if (i < 2 * BB) (&g_count[0][0])[i] = 0;
}

// ---------------- K0b: pre-split + pre-pack W1 ----------------
__global__ void prep_w_kernel(const float* __restrict__ W1) {
    int i = blockIdx.x * blockDim.x + threadIdx.x;
    if (i >= HH * 64) return;
    int n  = i >> 6;
    int kp = i & 63;
    float w0 = W1[(2 * kp)     * HH + n];
    float w1 = W1[(2 * kp + 1) * HH + n];
    uint32_t hi = bf16x2_pack(w1, w0);
    float h0 = bf16_lo_as_f32(hi);
    float h1 = bf16_hi_as_f32(hi);
    uint32_t lo = bf16x2_pack(w1 - h1, w0 - h0);
    g_wb_hi[i] = hi;
    g_wb_lo[i] = lo;
}

// ---------------- K1: mma.sync bf16x3 score kernel (256 thr / 8 warps / 128-row tile) ----------------
#define SMEM_WORDS (TILE * XS_STRIDE + 2 * (HH * WB_STRIDE) + 64 + 64)

__global__ __launch_bounds__(256) void score_mma_kernel(
    const float* __restrict__ x1, const float* __restrict__ x2,
    const int* __restrict__ bA, const int* __restrict__ bB,
    const float* __restrict__ b1v, const float* __restrict__ W2)
{
    extern __shared__ float sm[];
    float*    xs  = sm;
    uint32_t* swh = (uint32_t*)(xs + TILE * XS_STRIDE);
    uint32_t* swl = swh + HH * WB_STRIDE;
    float*    b1s = (float*)(swl + HH * WB_STRIDE);
    float*    w2s = b1s + 64;

    const int tid  = threadIdx.x;
    const int wid  = tid >> 5;      // 0..7, each warp owns 16 rows
    const int lane = tid & 31;
    const int g    = lane >> 2;
    const int tq   = lane & 3;
    const int t    = blockIdx.y;
    const float* x = t ? x2 : x1;
    const int* batch = t ? bB : bA;
    const int n0   = blockIdx.x * TILE;

    // stage packed W (hi+lo): 4096 u32 each
    #pragma unroll
    for (int m = 0; m < 16; ++m) {
        int j = tid + 256 * m;
        int n  = j >> 6;
        int kp = j & 63;
        swh[n * WB_STRIDE + kp] = g_wb_hi[j];
        swl[n * WB_STRIDE + kp] = g_wb_lo[j];
    }
    if (tid < HH) { b1s[tid] = b1v[tid]; w2s[tid] = W2[tid]; }

    // stage x tile [128 nodes x 128 f] into xs[r][k] stride 132 (sequential, coalesced)
    #pragma unroll
    for (int m = 0; m < 16; ++m) {
        int idx = m * 256 + tid;
        int r = idx >> 5;
        int q = idx & 31;
        int node = n0 + r;
        float4 v = make_float4(0.f, 0.f, 0.f, 0.f);
        if (node < NN) v = ((const float4*)x)[node * 32 + q];
        *(float4*)&xs[r * XS_STRIDE + q * 4] = v;
    }
    __syncthreads();

    // GEMM: warp computes rows [wid*16, wid*16+16) x 64 hidden
    const int base = wid * 16;
    float acc[8][4];
    #pragma unroll
    for (int n = 0; n < 8; ++n)
        #pragma unroll
        for (int c = 0; c < 4; ++c) acc[n][c] = 0.0f;

    #pragma unroll
    for (int kt = 0; kt < 8; ++kt) {
        const int k0  = kt * 16;
        const int kp0 = kt * 8;

        uint32_t bh[8][2], bl[8][2];
        #pragma unroll
        for (int n = 0; n < 8; ++n) {
            int row = (n * 8 + g) * WB_STRIDE + kp0 + tq;
            bh[n][0] = swh[row];
            bh[n][1] = swh[row + 4];
            bl[n][0] = swl[row];
            bl[n][1] = swl[row + 4];
        }

        const int r = base + g;
        float2 q0 = *(const float2*)&xs[r       * XS_STRIDE + k0 + 2 * tq];
        float2 q1 = *(const float2*)&xs[(r + 8) * XS_STRIDE + k0 + 2 * tq];
        float2 q2 = *(const float2*)&xs[r       * XS_STRIDE + k0 + 2 * tq + 8];
        float2 q3 = *(const float2*)&xs[(r + 8) * XS_STRIDE + k0 + 2 * tq + 8];

        uint32_t ahi[4], alo[4];
        split2(q0, ahi[0], alo[0]);
        split2(q1, ahi[1], alo[1]);
        split2(q2, ahi[2], alo[2]);
        split2(q3, ahi[3], alo[3]);

        #pragma unroll
        for (int n = 0; n < 8; ++n) {
            mma_bf16(acc[n], ahi, bh[n]);
            mma_bf16(acc[n], ahi, bl[n]);
            mma_bf16(acc[n], alo, bh[n]);
        }
    }

    // epilogue: tanh + W2 dot, butterfly over the 4 lanes holding each row
    #pragma unroll
    for (int half = 0; half < 2; ++half) {
        float s = 0.0f;
        #pragma unroll
        for (int n = 0; n < 8; ++n) {
            #pragma unroll
            for (int c = 0; c < 2; ++c) {
                int col = n * 8 + 2 * tq + c;
                float h = acc[n][half * 2 + c] + b1s[col];
                s = fmaf(tanh_fast(h), w2s[col], s);
            }
        }
        s += __shfl_xor_sync(0xffffffffu, s, 1);
        s += __shfl_xor_sync(0xffffffffu, s, 2);
        if (tq == 0) {
            int node = n0 + base + half * 8 + g;
            if (node < NN) {
                g_e[t][node] = __expf(s);
                atomicAdd(&g_count[t][batch[node]], 1);
            }
        }
    }
}

// ---------------- K2: exclusive prefix scan over segments ----------------
__global__ void scan_kernel() {
    __shared__ int ss[BB];
    int tid = threadIdx.x;
    for (int t = 0; t < 2; ++t) {
        int v = g_count[t][tid];
        ss[tid] = v;
        __syncthreads();
        for (int d = 1; d < BB; d <<= 1) {
            int add = (tid >= d) ? ss[tid - d] : 0;
            __syncthreads();
            ss[tid] += add;
            __syncthreads();
        }
        int incl = ss[tid];
        g_offset[t][tid] = incl - v;
        g_cursor[t][tid] = incl - v;
        if (tid == BB - 1) g_offset[t][BB] = incl;
        __syncthreads();
    }
}

// ---------------- K3: scatter (vectorized loads, fused 8B pair store) ----------------
__global__ __launch_bounds__(512) void scatter_kernel(
    const int* __restrict__ bA, const int* __restrict__ bB)
{
    int t = blockIdx.y;
    int i0 = (blockIdx.x * 512 + threadIdx.x) * 4;
    if (i0 >= NN) return;                     // NN % 4 == 0, no partial quad
    const int* batch = t ? bB : bA;
    int4   bv = *(const int4*)&batch[i0];
    float4 ev = *(const float4*)&g_e[t][i0];
    int p0 = atomicAdd(&g_cursor[t][bv.x], 1);
    int p1 = atomicAdd(&g_cursor[t][bv.y], 1);
    int p2 = atomicAdd(&g_cursor[t][bv.z], 1);
    int p3 = atomicAdd(&g_cursor[t][bv.w], 1);
    g_pair[t][p0] = make_float2(__int_as_float(i0 + 0), ev.x);
    g_pair[t][p1] = make_float2(__int_as_float(i0 + 1), ev.y);
    g_pair[t][p2] = make_float2(__int_as_float(i0 + 2), ev.z);
    g_pair[t][p3] = make_float2(__int_as_float(i0 + 3), ev.w);
}

// ---------------- K4: per-segment weighted pooling (16 warps, 32 rows in flight) ----------------
__global__ __launch_bounds__(512) void pool_kernel(
    const float* __restrict__ x1, const float* __restrict__ x2,
    float* __restrict__ out)
{
    const int t = blockIdx.y;
    const int b = blockIdx.x;
    const float4* x4 = (const float4*)(t ? x2 : x1);
    const int start = g_offset[t][b];
    const int end   = g_offset[t][b + 1];
    const int w = threadIdx.x >> 5;    // warp 0..15 -> row slot
    const int l = threadIdx.x & 31;    // lane -> feature quad

    float4 acc = make_float4(0.f, 0.f, 0.f, 0.f);
    float  es  = 0.0f;

    #pragma unroll 2
    for (int p = start + w; p < end; p += 16) {
        float2 pr = g_pair[t][p];
        int   n = __float_as_int(pr.x);
        float e = pr.y;
        float4 xv = x4[n * 32 + l];
        acc.x = fmaf(e, xv.x, acc.x);
        acc.y = fmaf(e, xv.y, acc.y);
        acc.z = fmaf(e, xv.z, acc.z);
        acc.w = fmaf(e, xv.w, acc.w);
        es += e;
    }

    __shared__ float sacc[16][FF];
    __shared__ float ses[16];
    *(float4*)&sacc[w][4 * l] = acc;
    if (l == 0) ses[w] = es;
    __syncthreads();

    if (threadIdx.x < FF && end > start) {
        int f = threadIdx.x;
        float tot = 0.0f;
        #pragma unroll
        for (int g2 = 0; g2 < 16; ++g2) tot += sacc[g2][f];
        float s = 0.0f;
        #pragma unroll
        for (int g2 = 0; g2 < 16; ++g2) s += ses[g2];
        atomicAdd(&out[b * FF + f], 0.5f * tot / s);
    }
}

// ---------------- launch ----------------
extern "C" void kernel_launch(void* const* d_in, const int* in_sizes, int n_in,
                              void* d_out, int out_size) {
    const float *x1 = 0, *x2 = 0, *W1 = 0, *b1v = 0, *W2 = 0;
    const int *bt1 = 0, *bt2 = 0;
    for (int k = 0; k < n_in; ++k) {
        long s = in_sizes[k];
        if (s == (long)NN * FF) { if (!x1) x1 = (const float*)d_in[k]; else if (!x2) x2 = (const float*)d_in[k]; }
        else if (s == NN)       { if (!bt1) bt1 = (const int*)d_in[k]; else if (!bt2) bt2 = (const int*)d_in[k]; }
        else if (s == FF * HH)  { W1 = (const float*)d_in[k]; }
        else if (s == HH)       { if (!b1v) b1v = (const float*)d_in[k]; else if (!W2) W2 = (const float*)d_in[k]; }
    }
    float* out = (float*)d_out;

    init_kernel<<<(BB * FF + 255) / 256, 256>>>(out);
    prep_w_kernel<<<(HH * 64 + 255) / 256, 256>>>(W1);

    const int smem_bytes = SMEM_WORDS * (int)sizeof(float);
    cudaFuncSetAttribute(score_mma_kernel, cudaFuncAttributeMaxDynamicSharedMemorySize, smem_bytes);
    dim3 g1((NN + TILE - 1) / TILE, 2);
    score_mma_kernel<<<g1, 256, smem_bytes>>>(x1, x2, bt1, bt2, b1v, W2);

    scan_kernel<<<1, BB>>>();

    dim3 g3((NN / 4 + 511) / 512, 2);
    scatter_kernel<<<g3, 512>>>(bt1, bt2);

    dim3 g4(BB, 2);
    pool_kernel<<<g4, 512>>>(x1, x2, out);
}